// round 16
// baseline (speedup 1.0000x reference)
#include <cuda_runtime.h>
#include <cuda_bf16.h>
#include <cstdint>

// Shapes (fixed by the problem)
#define BB   2
#define HQ   32
#define HK   8
#define SS   8192
#define DD   128
#define HID  128
#define BSZ  16
#define NB   512

// Scratch (allocation-free rule: __device__ globals)
__device__ float    g_qh[BB * HQ * NB * HID];    // 16.8 MB
__device__ float    g_kh[BB * HK * NB * HID];    //  4.2 MB
__device__ uint32_t g_pq[BB * HQ * NB * 256];    // pooled q, pre-split bf16 pairs (hi[128],lo[128])
__device__ uint32_t g_pk[BB * HK * NB * 256];    // pooled k, pre-split

// ---------------------------------------------------------------------------
// bf16 split helpers + mma.sync wrapper
// ---------------------------------------------------------------------------
__device__ __forceinline__ void mma_bf16(float* c, const uint32_t* a, const uint32_t* b) {
    asm volatile(
        "mma.sync.aligned.m16n8k16.row.col.f32.bf16.bf16.f32 "
        "{%0,%1,%2,%3}, {%4,%5,%6,%7}, {%8,%9}, {%0,%1,%2,%3};\n"
        : "+f"(c[0]), "+f"(c[1]), "+f"(c[2]), "+f"(c[3])
        : "r"(a[0]), "r"(a[1]), "r"(a[2]), "r"(a[3]), "r"(b[0]), "r"(b[1]));
}

__device__ __forceinline__ void split_pair(float x, float y, uint32_t& hi, uint32_t& lo) {
    __nv_bfloat16 hx = __float2bfloat16(x);
    __nv_bfloat16 hy = __float2bfloat16(y);
    float lx = x - __bfloat162float(hx);
    float ly = y - __bfloat162float(hy);
    __nv_bfloat162 h2 = __halves2bfloat162(hx, hy);          // low half = x-elem
    __nv_bfloat162 l2 = __floats2bfloat162_rn(lx, ly);
    hi = *(uint32_t*)&h2;
    lo = *(uint32_t*)&l2;
}

__device__ __forceinline__ uint32_t smem_u32(const void* p) {
    uint32_t a;
    asm("{ .reg .u64 t; cvta.to.shared.u64 t, %1; cvt.u32.u64 %0, t; }" : "=r"(a) : "l"(p));
    return a;
}

// ---------------------------------------------------------------------------
// Kernel 0: pooling (mean & max over BSZ=16), streaming at full occupancy.
// Emits PRE-SPLIT bf16 hi/lo pairs: per (b,h,n): hi pairs [0..127], lo [128..255]
// (pairs 0..63 = mean, 64..127 = max).
// ---------------------------------------------------------------------------
__global__ __launch_bounds__(256)
void pool_kernel(const float* __restrict__ q, const float* __restrict__ kk)
{
    int idx = blockIdx.x * 256 + threadIdx.x;
    const float* x;
    uint32_t* dst;
    int NH;
    if (idx < BB * HQ * NB * 32) {
        x = q;  dst = g_pq;  NH = HQ;
    } else {
        idx -= BB * HQ * NB * 32;
        x = kk; dst = g_pk;  NH = HK;
    }
    const int d4 = idx & 31;
    const int n  = (idx >> 5) & (NB - 1);
    const int hb = idx >> 14;
    const int h  = hb % NH;
    const int b  = hb / NH;

    const float* xp = x + (((size_t)(b * NH + h)) * SS + (size_t)n * BSZ) * DD + d4 * 4;
    float4 s  = make_float4(0.f, 0.f, 0.f, 0.f);
    float4 mx = make_float4(-3.0e38f, -3.0e38f, -3.0e38f, -3.0e38f);
    #pragma unroll
    for (int i = 0; i < BSZ; i++) {
        float4 v = *(const float4*)&xp[i * DD];
        s.x += v.x;  s.y += v.y;  s.z += v.z;  s.w += v.w;
        mx.x = fmaxf(mx.x, v.x);  mx.y = fmaxf(mx.y, v.y);
        mx.z = fmaxf(mx.z, v.z);  mx.w = fmaxf(mx.w, v.w);
    }
    uint32_t* o = dst + (((size_t)(b * NH + h)) * NB + n) * 256;
    uint32_t h0, l0, h1, l1;
    split_pair(s.x * (1.0f / BSZ), s.y * (1.0f / BSZ), h0, l0);
    split_pair(s.z * (1.0f / BSZ), s.w * (1.0f / BSZ), h1, l1);
    *(uint2*)&o[d4 * 2]       = make_uint2(h0, h1);          // mean hi
    *(uint2*)&o[128 + d4 * 2] = make_uint2(l0, l1);          // mean lo
    split_pair(mx.x, mx.y, h0, l0);
    split_pair(mx.z, mx.w, h1, l1);
    *(uint2*)&o[64 + d4 * 2]  = make_uint2(h0, h1);          // max hi
    *(uint2*)&o[192 + d4 * 2] = make_uint2(l0, l1);          // max lo
}

// ---------------------------------------------------------------------------
// Kernel 1: projection (tensor cores) + RoPE, reading pre-split pooled data.
// W streamed with cp.async double buffering (8 chunks x 32 cc), split inline
// during fragment construction. One CTA = 64 n-rows of one (b,h); Q/K merged.
// ---------------------------------------------------------------------------
#define ASTR 132   // A pair stride (== 4 mod 32 -> conflict-free fragments)
#define WFSTR 132  // fp32 W staging row stride (2*132 mod 32 == 8 -> conflict-free)
#define PROJ_SMEM_BYTES ((2 * 64 * ASTR + 2 * 32 * WFSTR) * 4)   // 101376

__global__ __launch_bounds__(256, 2)
void proj_mma_kernel(const float* __restrict__ wq,
                     const float* __restrict__ wk,
                     const float* __restrict__ cosb,
                     const float* __restrict__ sinb)
{
    extern __shared__ uint32_t sm[];
    uint32_t* sAh = sm;
    uint32_t* sAl = sm + 64 * ASTR;
    float*    sW  = (float*)(sm + 2 * 64 * ASTR);      // 2 x [32][WFSTR]

    const int bid0 = blockIdx.x;
    const bool isQ = bid0 < BB * HQ * 8;
    const int bid  = isQ ? bid0 : bid0 - BB * HQ * 8;
    const int NH   = isQ ? HQ : HK;
    const uint32_t* pool = isQ ? g_pq : g_pk;
    const float* w = isQ ? wq : wk;
    float* dst     = isQ ? g_qh : g_kh;

    const int mt8 = bid & 7;                 // NB/64 = 8 row tiles
    const int h   = (bid >> 3) % NH;
    const int b   = bid / (8 * NH);
    const int n0  = mt8 * 64;

    const int tid  = threadIdx.x;
    const int lane = tid & 31, wid = tid >> 5;
    const int wm = wid >> 2, wn = wid & 3;   // warp grid 2(m) x 4(n)
    const int g  = lane >> 2, tg = lane & 3;

    const float* wbase = w + (size_t)h * 256 * 128;
    const int wr = tid >> 5;                 // cp.async: row group (warp id 0..7)
    const int wc = (tid & 31);               // col4 0..31

    // ---- prefetch W chunk 0 ----
    {
        const uint32_t d0 = smem_u32(sW);
        #pragma unroll
        for (int rr = 0; rr < 4; rr++) {
            const int r = rr * 8 + wr;
            asm volatile("cp.async.cg.shared.global [%0], [%1], 16;"
                :: "r"(d0 + (uint32_t)((r * WFSTR + wc * 4) * 4)),
                   "l"(wbase + (size_t)r * 128 + wc * 4) : "memory");
        }
        asm volatile("cp.async.commit_group;" ::: "memory");
    }

    // ---- load pre-split A tile [64 x 128 pairs hi/lo] (pure uint4 copy) ----
    #pragma unroll
    for (int it = 0; it < 16; it++) {
        const int idx = tid + it * 256;      // 0..4095
        const int n = idx >> 6;              // 0..63
        const int j = idx & 63;              // uint4 index within row (64 = 32 hi + 32 lo)
        uint4 v = *(const uint4*)&pool[(((size_t)(b * NH + h)) * NB + n0 + n) * 256 + j * 4];
        if (j < 32) *(uint4*)&sAh[n * ASTR + j * 4] = v;
        else        *(uint4*)&sAl[n * ASTR + (j - 32) * 4] = v;
    }

    float acc[2][4][4];
    #pragma unroll
    for (int i = 0; i < 2; i++)
        #pragma unroll
        for (int j = 0; j < 4; j++)
            #pragma unroll
            for (int r = 0; r < 4; r++) acc[i][j][r] = 0.f;

    for (int c = 0; c < 8; c++) {            // 8 chunks of 32 cc
        if (c < 7) {                         // prefetch next chunk
            const uint32_t d1 = smem_u32(sW + ((c + 1) & 1) * 32 * WFSTR);
            const float* src = wbase + (size_t)(c + 1) * 32 * 128;
            #pragma unroll
            for (int rr = 0; rr < 4; rr++) {
                const int r = rr * 8 + wr;
                asm volatile("cp.async.cg.shared.global [%0], [%1], 16;"
                    :: "r"(d1 + (uint32_t)((r * WFSTR + wc * 4) * 4)),
                       "l"(src + (size_t)r * 128 + wc * 4) : "memory");
            }
            asm volatile("cp.async.commit_group;" ::: "memory");
            asm volatile("cp.async.wait_group 1;" ::: "memory");
        } else {
            asm volatile("cp.async.wait_group 0;" ::: "memory");
        }
        __syncthreads();

        const float* Wb = sW + (c & 1) * 32 * WFSTR;

        #pragma unroll
        for (int ksl = 0; ksl < 2; ksl++) {  // two k16 steps per chunk
            const int ka = c * 16 + ksl * 8; // A pair offset (128 pairs total)
            uint32_t Ah[2][4], Al[2][4], Bh[4][2], Bl[4][2];

            #pragma unroll
            for (int mt = 0; mt < 2; mt++) {
                const uint32_t* ph = &sAh[(wm * 32 + mt * 16 + g) * ASTR + ka + tg];
                const uint32_t* pl = &sAl[(wm * 32 + mt * 16 + g) * ASTR + ka + tg];
                Ah[mt][0] = ph[0];  Ah[mt][1] = ph[8 * ASTR];
                Ah[mt][2] = ph[4];  Ah[mt][3] = ph[8 * ASTR + 4];
                Al[mt][0] = pl[0];  Al[mt][1] = pl[8 * ASTR];
                Al[mt][2] = pl[4];  Al[mt][3] = pl[8 * ASTR + 4];
            }
            const int r1 = 2 * (ksl * 8 + tg);   // first cc row of pair 1
            #pragma unroll
            for (int nt = 0; nt < 4; nt++) {
                const int n = wn * 32 + nt * 8 + g;
                split_pair(Wb[r1 * WFSTR + n],       Wb[(r1 + 1) * WFSTR + n], Bh[nt][0], Bl[nt][0]);
                split_pair(Wb[(r1 + 8) * WFSTR + n], Wb[(r1 + 9) * WFSTR + n], Bh[nt][1], Bl[nt][1]);
            }

            #pragma unroll
            for (int mt = 0; mt < 2; mt++)
                #pragma unroll
                for (int nt = 0; nt < 4; nt++) {
                    mma_bf16(acc[mt][nt], Ah[mt], Bh[nt]);
                    mma_bf16(acc[mt][nt], Ah[mt], Bl[nt]);
                    mma_bf16(acc[mt][nt], Al[mt], Bh[nt]);
                }
        }
        __syncthreads();
    }

    // ---- epilogue: stage fp32 tile, RoPE, write ----
    float* stage = (float*)sm;               // 64 x ASTR floats (fits in sAh+sAl)
    #pragma unroll
    for (int mt = 0; mt < 2; mt++)
        #pragma unroll
        for (int nt = 0; nt < 4; nt++) {
            const int row = wm * 32 + mt * 16 + g;
            const int col = wn * 32 + nt * 8 + tg * 2;
            stage[row * ASTR + col]           = acc[mt][nt][0];
            stage[row * ASTR + col + 1]       = acc[mt][nt][1];
            stage[(row + 8) * ASTR + col]     = acc[mt][nt][2];
            stage[(row + 8) * ASTR + col + 1] = acc[mt][nt][3];
        }
    __syncthreads();

    #pragma unroll
    for (int it = 0; it < 16; it++) {
        const int idx = tid + it * 256;
        const int n  = idx >> 6;
        const int d  = (idx & 63) * 2;
        float2 v = *(const float2*)&stage[n * ASTR + d];
        float2 r;
        if (d < 64) {
            r.x = -stage[n * ASTR + d + 64];
            r.y = -stage[n * ASTR + d + 65];
        } else {
            r.x = stage[n * ASTR + d - 64];
            r.y = stage[n * ASTR + d - 63];
        }
        const size_t ci = ((size_t)b * NB + n0 + n) * HID + d;
        float2 c  = *(const float2*)&cosb[ci];
        float2 sn = *(const float2*)&sinb[ci];
        float2 o;
        o.x = v.x * c.x + r.x * sn.x;
        o.y = v.y * c.y + r.y * sn.y;
        *(float2*)&dst[(((size_t)(b * NH + h)) * NB + n0 + n) * HID + d] = o;
    }
}

// ---------------------------------------------------------------------------
// Kernel 2: block-causal logits via mma.sync bf16 split (unchanged).
// ---------------------------------------------------------------------------
#define LSTR 20

__global__ __launch_bounds__(256, 1)
void logits_mma_kernel(float* __restrict__ out)
{
    __shared__ uint32_t sAh[128 * LSTR], sAl[128 * LSTR];
    __shared__ uint32_t sBh[128 * LSTR], sBl[128 * LSTR];

    const int b  = blockIdx.z;
    const int h  = blockIdx.y;
    const int ti = blockIdx.x;
    const int mt4 = (ti >= 6) ? 3 : (ti >= 3) ? 2 : (ti >= 1) ? 1 : 0;
    const int jt  = ti - mt4 * (mt4 + 1) / 2;
    const int m0  = mt4 * 128;
    const int j0  = jt * 128;

    const float* Ag = g_qh + (((size_t)(b * HQ + h)) * NB + m0) * HID;
    const float* Bg = g_kh + (((size_t)(b * HK + h / (HQ / HK))) * NB + j0) * HID;

    const int tid  = threadIdx.x;
    const int lane = tid & 31, wid = tid >> 5;
    const int wm = wid >> 2, wn = wid & 3;
    const int g  = lane >> 2, tg = lane & 3;

    float acc[4][4][4];
    #pragma unroll
    for (int i = 0; i < 4; i++)
        #pragma unroll
        for (int j = 0; j < 4; j++)
            #pragma unroll
            for (int r = 0; r < 4; r++) acc[i][j][r] = 0.f;

    const int lr0 = tid >> 3;
    const int lq  = tid & 7;

    for (int kc = 0; kc < 4; kc++) {
        __syncthreads();
        #pragma unroll
        for (int pass = 0; pass < 4; pass++) {
            const int r = pass * 32 + lr0;
            float4 va = *(const float4*)&Ag[(size_t)r * HID + kc * 32 + lq * 4];
            uint32_t h0, l0, h1, l1;
            split_pair(va.x, va.y, h0, l0);
            split_pair(va.z, va.w, h1, l1);
            sAh[r * LSTR + lq * 2 + 0] = h0;  sAh[r * LSTR + lq * 2 + 1] = h1;
            sAl[r * LSTR + lq * 2 + 0] = l0;  sAl[r * LSTR + lq * 2 + 1] = l1;

            float4 vb = *(const float4*)&Bg[(size_t)r * HID + kc * 32 + lq * 4];
            split_pair(vb.x, vb.y, h0, l0);
            split_pair(vb.z, vb.w, h1, l1);
            sBh[r * LSTR + lq * 2 + 0] = h0;  sBh[r * LSTR + lq * 2 + 1] = h1;
            sBl[r * LSTR + lq * 2 + 0] = l0;  sBl[r * LSTR + lq * 2 + 1] = l1;
        }
        __syncthreads();

        #pragma unroll
        for (int ks = 0; ks < 2; ks++) {
            const int kb = ks * 8;
            uint32_t Ah[4][4], Al[4][4], Bh[4][2], Bl[4][2];

            #pragma unroll
            for (int mt = 0; mt < 4; mt++) {
                const int r = wm * 64 + mt * 16 + g;
                const uint32_t* ph = &sAh[r * LSTR + kb + tg];
                const uint32_t* pl = &sAl[r * LSTR + kb + tg];
                Ah[mt][0] = ph[0];  Ah[mt][1] = ph[8 * LSTR];
                Ah[mt][2] = ph[4];  Ah[mt][3] = ph[8 * LSTR + 4];
                Al[mt][0] = pl[0];  Al[mt][1] = pl[8 * LSTR];
                Al[mt][2] = pl[4];  Al[mt][3] = pl[8 * LSTR + 4];
            }
            #pragma unroll
            for (int nt = 0; nt < 4; nt++) {
                const int n = wn * 32 + nt * 8 + g;
                const uint32_t* ph = &sBh[n * LSTR + kb + tg];
                const uint32_t* pl = &sBl[n * LSTR + kb + tg];
                Bh[nt][0] = ph[0];  Bh[nt][1] = ph[4];
                Bl[nt][0] = pl[0];  Bl[nt][1] = pl[4];
            }

            #pragma unroll
            for (int mt = 0; mt < 4; mt++)
                #pragma unroll
                for (int nt = 0; nt < 4; nt++) {
                    mma_bf16(acc[mt][nt], Ah[mt], Bh[nt]);
                    mma_bf16(acc[mt][nt], Ah[mt], Bl[nt]);
                    mma_bf16(acc[mt][nt], Al[mt], Bh[nt]);
                }
        }
    }

    const float scale = 0.08838834764831845f;
    #pragma unroll
    for (int mt = 0; mt < 4; mt++) {
        #pragma unroll
        for (int nt = 0; nt < 4; nt++) {
            const int row = m0 + wm * 64 + mt * 16 + g;
            const int col = j0 + wn * 32 + nt * 8 + tg * 2;
            float* p0 = out + (((size_t)(b * HQ + h)) * NB + row) * NB + col;
            *(float2*)p0 = make_float2(acc[mt][nt][0] * scale, acc[mt][nt][1] * scale);
            *(float2*)(p0 + 8 * NB) = make_float2(acc[mt][nt][2] * scale, acc[mt][nt][3] * scale);
        }
    }
}

// ---------------------------------------------------------------------------
// Kernel 3: masked softmax, one WARP per row; exp via exp2f.
// ---------------------------------------------------------------------------
__global__ __launch_bounds__(512)
void softmax_kernel(float* __restrict__ out)
{
    const int wid  = threadIdx.x >> 5;
    const int lane = threadIdx.x & 31;
    const int row  = blockIdx.x * 16 + wid;      // ((b*HQ+h)*NB + i)
    const int i    = row & (NB - 1);
    float* p = out + (size_t)row * NB;
    const float L2E = 1.4426950408889634f;

    float4 v[4];
    float mx = -3.0e38f;
    #pragma unroll
    for (int w = 0; w < 4; w++) {
        const int j = w * 128 + lane * 4;
        if (j <= i) {
            v[w] = *(const float4*)&p[j];
            if (j + 1 > i) v[w].y = -3.0e38f;
            if (j + 2 > i) v[w].z = -3.0e38f;
            if (j + 3 > i) v[w].w = -3.0e38f;
        } else {
            v[w] = make_float4(-3.0e38f, -3.0e38f, -3.0e38f, -3.0e38f);
        }
        mx = fmaxf(mx, fmaxf(fmaxf(v[w].x, v[w].y), fmaxf(v[w].z, v[w].w)));
    }
    #pragma unroll
    for (int o = 16; o; o >>= 1) mx = fmaxf(mx, __shfl_xor_sync(0xffffffffu, mx, o));

    float s = 0.f;
    #pragma unroll
    for (int w = 0; w < 4; w++) {
        v[w].x = (v[w].x > -1.0e38f) ? exp2f((v[w].x - mx) * L2E) : 0.f;
        v[w].y = (v[w].y > -1.0e38f) ? exp2f((v[w].y - mx) * L2E) : 0.f;
        v[w].z = (v[w].z > -1.0e38f) ? exp2f((v[w].z - mx) * L2E) : 0.f;
        v[w].w = (v[w].w > -1.0e38f) ? exp2f((v[w].w - mx) * L2E) : 0.f;
        s += v[w].x + v[w].y + v[w].z + v[w].w;
    }
    #pragma unroll
    for (int o = 16; o; o >>= 1) s += __shfl_xor_sync(0xffffffffu, s, o);

    const float inv = 1.0f / s;
    #pragma unroll
    for (int w = 0; w < 4; w++) {
        float4 o4;
        o4.x = v[w].x * inv;  o4.y = v[w].y * inv;
        o4.z = v[w].z * inv;  o4.w = v[w].w * inv;
        *(float4*)&p[w * 128 + lane * 4] = o4;
    }
}

// ---------------------------------------------------------------------------
extern "C" void kernel_launch(void* const* d_in, const int* in_sizes, int n_in,
                              void* d_out, int out_size)
{
    const float* q    = (const float*)d_in[0];
    const float* k    = (const float*)d_in[1];
    const float* cosb = (const float*)d_in[3];
    const float* sinb = (const float*)d_in[4];
    const float* wq   = (const float*)d_in[5];
    const float* wk   = (const float*)d_in[6];
    float* out = (float*)d_out;

    cudaFuncSetAttribute(proj_mma_kernel,
                         cudaFuncAttributeMaxDynamicSharedMemorySize, PROJ_SMEM_BYTES);

    // 0) pooling at full occupancy (pre-split bf16 output)
    const int pool_threads = (BB * HQ * NB * 32 + BB * HK * NB * 32);
    pool_kernel<<<pool_threads / 256, 256>>>(q, k);

    // 1) projection (tensor, cp.async W pipeline) + rope
    proj_mma_kernel<<<BB * HQ * 8 + BB * HK * 8, 256, PROJ_SMEM_BYTES>>>(
        wq, wk, cosb, sinb);

    // 2) causal logits on tensor cores (bf16 split x3, mma.sync)
    dim3 lg(10, HQ, BB);
    logits_mma_kernel<<<lg, 256>>>(out);

    // 3) masked softmax in place (warp per row)
    softmax_kernel<<<BB * HQ * NB / 16, 512>>>(out);
}

// round 17
// speedup vs baseline: 1.2045x; 1.2045x over previous
#include <cuda_runtime.h>
#include <cuda_bf16.h>
#include <cstdint>

// Shapes (fixed by the problem)
#define BB   2
#define HQ   32
#define HK   8
#define SS   8192
#define DD   128
#define HID  128
#define BSZ  16
#define NB   512

// Scratch (allocation-free rule: __device__ globals)
__device__ float    g_qh[BB * HQ * NB * HID];    // 16.8 MB
__device__ float    g_kh[BB * HK * NB * HID];    //  4.2 MB
__device__ uint32_t g_pq[BB * HQ * NB * 256];    // pooled q, pre-split bf16 pairs (hi[128],lo[128])
__device__ uint32_t g_pk[BB * HK * NB * 256];    // pooled k, pre-split
__device__ uint32_t g_wsh[(HQ + HK) * 128 * 128]; // W pre-split hi (q heads 0..31, k heads 32..39)
__device__ uint32_t g_wsl[(HQ + HK) * 128 * 128]; // W pre-split lo

// ---------------------------------------------------------------------------
// bf16 split helpers + mma.sync wrapper
// ---------------------------------------------------------------------------
__device__ __forceinline__ void mma_bf16(float* c, const uint32_t* a, const uint32_t* b) {
    asm volatile(
        "mma.sync.aligned.m16n8k16.row.col.f32.bf16.bf16.f32 "
        "{%0,%1,%2,%3}, {%4,%5,%6,%7}, {%8,%9}, {%0,%1,%2,%3};\n"
        : "+f"(c[0]), "+f"(c[1]), "+f"(c[2]), "+f"(c[3])
        : "r"(a[0]), "r"(a[1]), "r"(a[2]), "r"(a[3]), "r"(b[0]), "r"(b[1]));
}

__device__ __forceinline__ void split_pair(float x, float y, uint32_t& hi, uint32_t& lo) {
    __nv_bfloat16 hx = __float2bfloat16(x);
    __nv_bfloat16 hy = __float2bfloat16(y);
    float lx = x - __bfloat162float(hx);
    float ly = y - __bfloat162float(hy);
    __nv_bfloat162 h2 = __halves2bfloat162(hx, hy);          // low half = x-elem
    __nv_bfloat162 l2 = __floats2bfloat162_rn(lx, ly);
    hi = *(uint32_t*)&h2;
    lo = *(uint32_t*)&l2;
}

// ---------------------------------------------------------------------------
// Kernel W: pre-split projection weights into bf16 hi/lo planes (once).
// Layout: g_wsh[(hoff*128 + cp)*128 + d] = hi of (w[2cp][d], w[2cp+1][d]).
// ---------------------------------------------------------------------------
__global__ __launch_bounds__(256)
void wsplit_kernel(const float* __restrict__ wq, const float* __restrict__ wk)
{
    const int idx = blockIdx.x * 256 + threadIdx.x;   // (hoff, cp, d)
    const int d   = idx & 127;
    const int cp  = (idx >> 7) & 127;
    const int hh  = idx >> 14;                         // 0..39
    const float* w = (hh < HQ) ? (wq + (size_t)hh * 256 * 128)
                               : (wk + (size_t)(hh - HQ) * 256 * 128);
    uint32_t hi, lo;
    split_pair(w[(size_t)(2 * cp) * 128 + d], w[(size_t)(2 * cp + 1) * 128 + d], hi, lo);
    g_wsh[idx] = hi;
    g_wsl[idx] = lo;
}

// ---------------------------------------------------------------------------
// Kernel 0: pooling (mean & max over BSZ=16), streaming at full occupancy.
// Emits PRE-SPLIT bf16 hi/lo pairs: per (b,h,n): hi pairs [0..127], lo [128..255]
// (pairs 0..63 = mean, 64..127 = max).
// ---------------------------------------------------------------------------
__global__ __launch_bounds__(256)
void pool_kernel(const float* __restrict__ q, const float* __restrict__ kk)
{
    int idx = blockIdx.x * 256 + threadIdx.x;
    const float* x;
    uint32_t* dst;
    int NH;
    if (idx < BB * HQ * NB * 32) {
        x = q;  dst = g_pq;  NH = HQ;
    } else {
        idx -= BB * HQ * NB * 32;
        x = kk; dst = g_pk;  NH = HK;
    }
    const int d4 = idx & 31;
    const int n  = (idx >> 5) & (NB - 1);
    const int hb = idx >> 14;
    const int h  = hb % NH;
    const int b  = hb / NH;

    const float* xp = x + (((size_t)(b * NH + h)) * SS + (size_t)n * BSZ) * DD + d4 * 4;
    float4 s  = make_float4(0.f, 0.f, 0.f, 0.f);
    float4 mx = make_float4(-3.0e38f, -3.0e38f, -3.0e38f, -3.0e38f);
    #pragma unroll
    for (int i = 0; i < BSZ; i++) {
        float4 v = *(const float4*)&xp[i * DD];
        s.x += v.x;  s.y += v.y;  s.z += v.z;  s.w += v.w;
        mx.x = fmaxf(mx.x, v.x);  mx.y = fmaxf(mx.y, v.y);
        mx.z = fmaxf(mx.z, v.z);  mx.w = fmaxf(mx.w, v.w);
    }
    uint32_t* o = dst + (((size_t)(b * NH + h)) * NB + n) * 256;
    uint32_t h0, l0, h1, l1;
    split_pair(s.x * (1.0f / BSZ), s.y * (1.0f / BSZ), h0, l0);
    split_pair(s.z * (1.0f / BSZ), s.w * (1.0f / BSZ), h1, l1);
    *(uint2*)&o[d4 * 2]       = make_uint2(h0, h1);          // mean hi (pairs 2*d4, 2*d4+1)
    *(uint2*)&o[128 + d4 * 2] = make_uint2(l0, l1);          // mean lo
    split_pair(mx.x, mx.y, h0, l0);
    split_pair(mx.z, mx.w, h1, l1);
    *(uint2*)&o[64 + d4 * 2]  = make_uint2(h0, h1);          // max hi (pairs 64+2*d4, ..)
    *(uint2*)&o[192 + d4 * 2] = make_uint2(l0, l1);          // max lo
}

// ---------------------------------------------------------------------------
// Kernel 1: projection (tensor cores) + RoPE. Structure identical to R15:
// same smem layouts (ASTR/WSTR), same fragment loads, same MMA loop; only the
// A and W loads are now pure copies of pre-split data (no cvt ALU).
// ---------------------------------------------------------------------------
#define ASTR 132   // A pair stride (== 4 mod 32 -> conflict-free fragments)
#define WSTR 36    // W pair stride (== 4 mod 32)
#define PROJ_SMEM_BYTES ((2 * 64 * ASTR + 2 * 128 * WSTR) * 4)   // 104448

__global__ __launch_bounds__(256, 2)
void proj_mma_kernel(const float* __restrict__ cosb,
                     const float* __restrict__ sinb)
{
    extern __shared__ uint32_t sm[];
    uint32_t* sAh = sm;
    uint32_t* sAl = sm + 64 * ASTR;
    uint32_t* sWh = sm + 2 * 64 * ASTR;
    uint32_t* sWl = sm + 2 * 64 * ASTR + 128 * WSTR;

    const int bid0 = blockIdx.x;
    const bool isQ = bid0 < BB * HQ * 8;
    const int bid  = isQ ? bid0 : bid0 - BB * HQ * 8;
    const int NH   = isQ ? HQ : HK;
    const uint32_t* pool = isQ ? g_pq : g_pk;
    float* dst     = isQ ? g_qh : g_kh;

    const int mt8 = bid & 7;                 // NB/64 = 8 row tiles
    const int h   = (bid >> 3) % NH;
    const int b   = bid / (8 * NH);
    const int n0  = mt8 * 64;
    const int hoff = isQ ? h : (HQ + h);

    const int tid  = threadIdx.x;
    const int lane = tid & 31, wid = tid >> 5;
    const int wm = wid >> 2, wn = wid & 3;   // warp grid 2(m) x 4(n)
    const int g  = lane >> 2, tg = lane & 3;

    // ---- load pre-split A tile [64 rows x 128 pairs hi + 128 lo] (uint4 copy) ----
    #pragma unroll
    for (int it = 0; it < 16; it++) {
        const int idx = tid + it * 256;      // 0..4095
        const int n = idx >> 6;              // 0..63
        const int j = idx & 63;              // uint4 index (32 hi + 32 lo)
        uint4 v = *(const uint4*)&pool[(((size_t)(b * NH + h)) * NB + n0 + n) * 256 + j * 4];
        if (j < 32) *(uint4*)&sAh[n * ASTR + j * 4] = v;
        else        *(uint4*)&sAl[n * ASTR + (j - 32) * 4] = v;
    }
    __syncthreads();

    float acc[2][4][4];
    #pragma unroll
    for (int i = 0; i < 2; i++)
        #pragma unroll
        for (int j = 0; j < 4; j++)
            #pragma unroll
            for (int r = 0; r < 4; r++) acc[i][j][r] = 0.f;

    const uint32_t* whp = g_wsh + (size_t)hoff * 128 * 128;
    const uint32_t* wlp = g_wsl + (size_t)hoff * 128 * 128;

    for (int kc = 0; kc < 4; kc++) {         // 4 chunks of 64 cc (= 32 pairs)
        // ---- copy pre-split W chunk (32 pairs x 128 d) into smem ----
        #pragma unroll
        for (int it = 0; it < 16; it++) {
            const int idx = tid + it * 256;
            const int d  = idx & 127;
            const int cp = idx >> 7;         // 0..31 (local pair)
            const size_t gi = (size_t)(kc * 32 + cp) * 128 + d;
            sWh[d * WSTR + cp] = whp[gi];
            sWl[d * WSTR + cp] = wlp[gi];
        }
        __syncthreads();

        #pragma unroll
        for (int ksl = 0; ksl < 4; ksl++) {  // k16 steps within chunk
            const int ka = (kc * 4 + ksl) * 8;   // A pair offset (full K)
            const int kb = ksl * 8;              // W pair offset (chunk)
            uint32_t Ah[2][4], Al[2][4], Bh[4][2], Bl[4][2];

            #pragma unroll
            for (int mt = 0; mt < 2; mt++) {
                const uint32_t* ph = &sAh[(wm * 32 + mt * 16 + g) * ASTR + ka + tg];
                const uint32_t* pl = &sAl[(wm * 32 + mt * 16 + g) * ASTR + ka + tg];
                Ah[mt][0] = ph[0];  Ah[mt][1] = ph[8 * ASTR];
                Ah[mt][2] = ph[4];  Ah[mt][3] = ph[8 * ASTR + 4];
                Al[mt][0] = pl[0];  Al[mt][1] = pl[8 * ASTR];
                Al[mt][2] = pl[4];  Al[mt][3] = pl[8 * ASTR + 4];
            }
            #pragma unroll
            for (int nt = 0; nt < 4; nt++) {
                const uint32_t* ph = &sWh[(wn * 32 + nt * 8 + g) * WSTR + kb + tg];
                const uint32_t* pl = &sWl[(wn * 32 + nt * 8 + g) * WSTR + kb + tg];
                Bh[nt][0] = ph[0];  Bh[nt][1] = ph[4];
                Bl[nt][0] = pl[0];  Bl[nt][1] = pl[4];
            }

            #pragma unroll
            for (int mt = 0; mt < 2; mt++)
                #pragma unroll
                for (int nt = 0; nt < 4; nt++) {
                    mma_bf16(acc[mt][nt], Ah[mt], Bh[nt]);
                    mma_bf16(acc[mt][nt], Ah[mt], Bl[nt]);
                    mma_bf16(acc[mt][nt], Al[mt], Bh[nt]);
                }
        }
        __syncthreads();
    }

    // ---- epilogue: stage fp32 tile, RoPE, write ----
    float* stage = (float*)sm;               // 64 x ASTR floats (fits in sAh+sAl)
    #pragma unroll
    for (int mt = 0; mt < 2; mt++)
        #pragma unroll
        for (int nt = 0; nt < 4; nt++) {
            const int row = wm * 32 + mt * 16 + g;
            const int col = wn * 32 + nt * 8 + tg * 2;
            stage[row * ASTR + col]           = acc[mt][nt][0];
            stage[row * ASTR + col + 1]       = acc[mt][nt][1];
            stage[(row + 8) * ASTR + col]     = acc[mt][nt][2];
            stage[(row + 8) * ASTR + col + 1] = acc[mt][nt][3];
        }
    __syncthreads();

    #pragma unroll
    for (int it = 0; it < 16; it++) {
        const int idx = tid + it * 256;
        const int n  = idx >> 6;
        const int d  = (idx & 63) * 2;
        float2 v = *(const float2*)&stage[n * ASTR + d];
        float2 r;
        if (d < 64) {
            r.x = -stage[n * ASTR + d + 64];
            r.y = -stage[n * ASTR + d + 65];
        } else {
            r.x = stage[n * ASTR + d - 64];
            r.y = stage[n * ASTR + d - 63];
        }
        const size_t ci = ((size_t)b * NB + n0 + n) * HID + d;
        float2 c  = *(const float2*)&cosb[ci];
        float2 sn = *(const float2*)&sinb[ci];
        float2 o;
        o.x = v.x * c.x + r.x * sn.x;
        o.y = v.y * c.y + r.y * sn.y;
        *(float2*)&dst[(((size_t)(b * NH + h)) * NB + n0 + n) * HID + d] = o;
    }
}

// ---------------------------------------------------------------------------
// Kernel 2: block-causal logits via mma.sync bf16 split (unchanged).
// ---------------------------------------------------------------------------
#define LSTR 20

__global__ __launch_bounds__(256, 1)
void logits_mma_kernel(float* __restrict__ out)
{
    __shared__ uint32_t sAh[128 * LSTR], sAl[128 * LSTR];
    __shared__ uint32_t sBh[128 * LSTR], sBl[128 * LSTR];

    const int b  = blockIdx.z;
    const int h  = blockIdx.y;
    const int ti = blockIdx.x;
    const int mt4 = (ti >= 6) ? 3 : (ti >= 3) ? 2 : (ti >= 1) ? 1 : 0;
    const int jt  = ti - mt4 * (mt4 + 1) / 2;
    const int m0  = mt4 * 128;
    const int j0  = jt * 128;

    const float* Ag = g_qh + (((size_t)(b * HQ + h)) * NB + m0) * HID;
    const float* Bg = g_kh + (((size_t)(b * HK + h / (HQ / HK))) * NB + j0) * HID;

    const int tid  = threadIdx.x;
    const int lane = tid & 31, wid = tid >> 5;
    const int wm = wid >> 2, wn = wid & 3;
    const int g  = lane >> 2, tg = lane & 3;

    float acc[4][4][4];
    #pragma unroll
    for (int i = 0; i < 4; i++)
        #pragma unroll
        for (int j = 0; j < 4; j++)
            #pragma unroll
            for (int r = 0; r < 4; r++) acc[i][j][r] = 0.f;

    const int lr0 = tid >> 3;
    const int lq  = tid & 7;

    for (int kc = 0; kc < 4; kc++) {
        __syncthreads();
        #pragma unroll
        for (int pass = 0; pass < 4; pass++) {
            const int r = pass * 32 + lr0;
            float4 va = *(const float4*)&Ag[(size_t)r * HID + kc * 32 + lq * 4];
            uint32_t h0, l0, h1, l1;
            split_pair(va.x, va.y, h0, l0);
            split_pair(va.z, va.w, h1, l1);
            sAh[r * LSTR + lq * 2 + 0] = h0;  sAh[r * LSTR + lq * 2 + 1] = h1;
            sAl[r * LSTR + lq * 2 + 0] = l0;  sAl[r * LSTR + lq * 2 + 1] = l1;

            float4 vb = *(const float4*)&Bg[(size_t)r * HID + kc * 32 + lq * 4];
            split_pair(vb.x, vb.y, h0, l0);
            split_pair(vb.z, vb.w, h1, l1);
            sBh[r * LSTR + lq * 2 + 0] = h0;  sBh[r * LSTR + lq * 2 + 1] = h1;
            sBl[r * LSTR + lq * 2 + 0] = l0;  sBl[r * LSTR + lq * 2 + 1] = l1;
        }
        __syncthreads();

        #pragma unroll
        for (int ks = 0; ks < 2; ks++) {
            const int kb = ks * 8;
            uint32_t Ah[4][4], Al[4][4], Bh[4][2], Bl[4][2];

            #pragma unroll
            for (int mt = 0; mt < 4; mt++) {
                const int r = wm * 64 + mt * 16 + g;
                const uint32_t* ph = &sAh[r * LSTR + kb + tg];
                const uint32_t* pl = &sAl[r * LSTR + kb + tg];
                Ah[mt][0] = ph[0];  Ah[mt][1] = ph[8 * LSTR];
                Ah[mt][2] = ph[4];  Ah[mt][3] = ph[8 * LSTR + 4];
                Al[mt][0] = pl[0];  Al[mt][1] = pl[8 * LSTR];
                Al[mt][2] = pl[4];  Al[mt][3] = pl[8 * LSTR + 4];
            }
            #pragma unroll
            for (int nt = 0; nt < 4; nt++) {
                const int n = wn * 32 + nt * 8 + g;
                const uint32_t* ph = &sBh[n * LSTR + kb + tg];
                const uint32_t* pl = &sBl[n * LSTR + kb + tg];
                Bh[nt][0] = ph[0];  Bh[nt][1] = ph[4];
                Bl[nt][0] = pl[0];  Bl[nt][1] = pl[4];
            }

            #pragma unroll
            for (int mt = 0; mt < 4; mt++)
                #pragma unroll
                for (int nt = 0; nt < 4; nt++) {
                    mma_bf16(acc[mt][nt], Ah[mt], Bh[nt]);
                    mma_bf16(acc[mt][nt], Ah[mt], Bl[nt]);
                    mma_bf16(acc[mt][nt], Al[mt], Bh[nt]);
                }
        }
    }

    const float scale = 0.08838834764831845f;
    #pragma unroll
    for (int mt = 0; mt < 4; mt++) {
        #pragma unroll
        for (int nt = 0; nt < 4; nt++) {
            const int row = m0 + wm * 64 + mt * 16 + g;
            const int col = j0 + wn * 32 + nt * 8 + tg * 2;
            float* p0 = out + (((size_t)(b * HQ + h)) * NB + row) * NB + col;
            *(float2*)p0 = make_float2(acc[mt][nt][0] * scale, acc[mt][nt][1] * scale);
            *(float2*)(p0 + 8 * NB) = make_float2(acc[mt][nt][2] * scale, acc[mt][nt][3] * scale);
        }
    }
}

// ---------------------------------------------------------------------------
// Kernel 3: masked softmax, one WARP per row (R15 version, expf).
// ---------------------------------------------------------------------------
__global__ __launch_bounds__(512)
void softmax_kernel(float* __restrict__ out)
{
    const int wid  = threadIdx.x >> 5;
    const int lane = threadIdx.x & 31;
    const int row  = blockIdx.x * 16 + wid;      // ((b*HQ+h)*NB + i)
    const int i    = row & (NB - 1);
    float* p = out + (size_t)row * NB;

    float4 v[4];
    float mx = -3.0e38f;
    #pragma unroll
    for (int w = 0; w < 4; w++) {
        const int j = w * 128 + lane * 4;
        if (j <= i) {
            v[w] = *(const float4*)&p[j];
            if (j + 1 > i) v[w].y = -3.0e38f;
            if (j + 2 > i) v[w].z = -3.0e38f;
            if (j + 3 > i) v[w].w = -3.0e38f;
        } else {
            v[w] = make_float4(-3.0e38f, -3.0e38f, -3.0e38f, -3.0e38f);
        }
        mx = fmaxf(mx, fmaxf(fmaxf(v[w].x, v[w].y), fmaxf(v[w].z, v[w].w)));
    }
    #pragma unroll
    for (int o = 16; o; o >>= 1) mx = fmaxf(mx, __shfl_xor_sync(0xffffffffu, mx, o));

    float s = 0.f;
    #pragma unroll
    for (int w = 0; w < 4; w++) {
        v[w].x = (v[w].x > -1.0e38f) ? expf(v[w].x - mx) : 0.f;
        v[w].y = (v[w].y > -1.0e38f) ? expf(v[w].y - mx) : 0.f;
        v[w].z = (v[w].z > -1.0e38f) ? expf(v[w].z - mx) : 0.f;
        v[w].w = (v[w].w > -1.0e38f) ? expf(v[w].w - mx) : 0.f;
        s += v[w].x + v[w].y + v[w].z + v[w].w;
    }
    #pragma unroll
    for (int o = 16; o; o >>= 1) s += __shfl_xor_sync(0xffffffffu, s, o);

    const float inv = 1.0f / s;
    #pragma unroll
    for (int w = 0; w < 4; w++) {
        float4 o4;
        o4.x = v[w].x * inv;  o4.y = v[w].y * inv;
        o4.z = v[w].z * inv;  o4.w = v[w].w * inv;
        *(float4*)&p[w * 128 + lane * 4] = o4;
    }
}

// ---------------------------------------------------------------------------
extern "C" void kernel_launch(void* const* d_in, const int* in_sizes, int n_in,
                              void* d_out, int out_size)
{
    const float* q    = (const float*)d_in[0];
    const float* k    = (const float*)d_in[1];
    const float* cosb = (const float*)d_in[3];
    const float* sinb = (const float*)d_in[4];
    const float* wq   = (const float*)d_in[5];
    const float* wk   = (const float*)d_in[6];
    float* out = (float*)d_out;

    cudaFuncSetAttribute(proj_mma_kernel,
                         cudaFuncAttributeMaxDynamicSharedMemorySize, PROJ_SMEM_BYTES);

    // W) pre-split weights (tiny)
    wsplit_kernel<<<(HQ + HK) * 128 * 128 / 256, 256>>>(wq, wk);

    // 0) pooling at full occupancy (pre-split bf16 output)
    const int pool_threads = (BB * HQ * NB * 32 + BB * HK * NB * 32);
    pool_kernel<<<pool_threads / 256, 256>>>(q, k);

    // 1) projection (tensor) + rope — pure-copy prologues
    proj_mma_kernel<<<BB * HQ * 8 + BB * HK * 8, 256, PROJ_SMEM_BYTES>>>(cosb, sinb);

    // 2) causal logits on tensor cores (bf16 split x3, mma.sync)
    dim3 lg(10, HQ, BB);
    logits_mma_kernel<<<lg, 256>>>(out);

    // 3) masked softmax in place (warp per row)
    softmax_kernel<<<BB * HQ * NB / 16, 512>>>(out);
}